// round 14
// baseline (speedup 1.0000x reference)
#include <cuda_runtime.h>

// DeepAttensionModule — SeFT cumulative set attention.
//  k_prep : fold query into W_key  -> Wkq[95,4], bq[4]
//  k_feat : 512 thr: warps 0-3 = 128 tokens; q=warp>>2 quarter-splits psi2/phi2; FFMA2
//  k_scan : per (b,h) 1024-thread block; max-free prefix sums of (e^pre, e^pre*phi)
//  k_rho  : grid 128 x 512 thr: layer1 K-split (ks=warp>>3), layer2 2tok x 8out; FFMA2

#define BATCH 16
#define SEQ   1024
#define NTOK  (BATCH*SEQ)
#define KEYIN 95

typedef unsigned long long u64;

__device__ __forceinline__ u64 pk2(float x, float y) {
    u64 r; asm("mov.b64 %0,{%1,%2};" : "=l"(r) : "f"(x), "f"(y)); return r;
}
__device__ __forceinline__ void upk2(u64 v, float& x, float& y) {
    asm("mov.b64 {%0,%1},%2;" : "=f"(x), "=f"(y) : "l"(v));
}
__device__ __forceinline__ void fma2(u64& d, u64 a, u64 b) {
    asm("fma.rn.f32x2 %0,%1,%2,%0;" : "+l"(d) : "l"(a), "l"(b));
}

__device__ float g_phi[NTOK*32];
__device__ float g_a[NTOK*4];
__device__ float g_xq[NTOK*4];
__device__ float g_agg[NTOK*128];
__device__ float g_Wkq[KEYIN*4];
__device__ float g_bq[4];

// ---------------------------------------------------------------- k_prep
__global__ void k_prep(const float* __restrict__ Wk, const float* __restrict__ bk,
                       const float* __restrict__ q) {
    int idx = threadIdx.x;
    if (idx < KEYIN*4) {
        int s = idx >> 2, h = idx & 3;
        float acc = 0.f;
        #pragma unroll
        for (int d = 0; d < 32; d++) acc += Wk[s*128 + h*32 + d] * q[h*32 + d];
        g_Wkq[idx] = acc;
    } else if (idx < KEYIN*4 + 4) {
        int h = idx - KEYIN*4;
        float acc = 0.f;
        #pragma unroll
        for (int d = 0; d < 32; d++) acc += bk[h*32 + d] * q[h*32 + d];
        g_bq[h] = acc;
    }
}

// ---------------------------------------------------------------- k_feat
// 512 threads, 128 tokens. Warp group (warp&3, lane) = token; q = warp>>2 is
// the psi2/phi2 output quarter. psi1/phi1 duplicated per quarter, chunk-consumed.
__global__ void __launch_bounds__(512) k_feat(
    const float* __restrict__ times, const float* __restrict__ values,
    const int*   __restrict__ meas,  const float* __restrict__ mask,
    const float* __restrict__ Wp1, const float* __restrict__ bp1,
    const float* __restrict__ Wp2, const float* __restrict__ bp2,
    const float* __restrict__ Wf1, const float* __restrict__ bf1,
    const float* __restrict__ Wf2, const float* __restrict__ bf2)
{
    __shared__ __align__(16) float sWp1[9*64];
    __shared__ float sMp1[64*22];
    __shared__ __align__(16) float sWp2[64*64];
    __shared__ __align__(16) float sWf1[9*32];
    __shared__ float sMf1[32*22];
    __shared__ __align__(16) float sWf2[32*32];
    __shared__ __align__(16) float sWkq[KEYIN*4 + 4];
    __shared__ float sq[128];
    __shared__ float sbp1[64], sbp2[64], sbf1[32], sbf2[32];
    __shared__ __align__(16) float sPa[4*128*4];

    int tid = threadIdx.x;
    for (int i = tid; i < 9*64;  i += 512) sWp1[i] = Wp1[i];
    for (int i = tid; i < 64*22; i += 512) { int j = i/22, m = i%22; sMp1[i] = Wp1[(9+m)*64 + j]; }
    for (int i = tid; i < 64*64; i += 512) sWp2[i] = Wp2[i];
    for (int i = tid; i < 9*32;  i += 512) sWf1[i] = Wf1[i];
    for (int i = tid; i < 32*22; i += 512) { int j = i/22, m = i%22; sMf1[i] = Wf1[(9+m)*32 + j]; }
    for (int i = tid; i < 32*32; i += 512) sWf2[i] = Wf2[i];
    for (int i = tid; i < KEYIN*4; i += 512) sWkq[i] = g_Wkq[i];
    if (tid < 64) { sbp1[tid] = bp1[tid]; sbp2[tid] = bp2[tid]; }
    if (tid < 32) { sbf1[tid] = bf1[tid]; sbf2[tid] = bf2[tid]; }
    __syncthreads();

    int warp = tid >> 5, lane = tid & 31;
    int q4   = warp >> 2;                   // output quarter 0..3
    int tok  = (warp & 3) * 32 + lane;
    int idx  = blockIdx.x*128 + tok;

    float t  = times[idx];
    float v  = values[idx];
    float mk = mask[idx];
    int   ms = meas[idx];
    int   m  = ms - 1;

    float x9[9];
    x9[0] = sinf(t);          x9[1] = cosf(t);
    x9[2] = sinf(t*0.1f);     x9[3] = cosf(t*0.1f);
    x9[4] = sinf(t*0.01f);    x9[5] = cosf(t*0.01f);
    x9[6] = sinf(t*0.001f);   x9[7] = cosf(t*0.001f);
    x9[8] = v;

    const ulonglong2* Wp1p = (const ulonglong2*)sWp1;
    const ulonglong2* Wp2p = (const ulonglong2*)sWp2;
    const ulonglong2* Wf1p = (const ulonglong2*)sWf1;
    const ulonglong2* Wf2p = (const ulonglong2*)sWf2;
    const float4*     sWkqv = (const float4*)sWkq;

    // ---- psi: outputs j in [q4*16, q4*16+16); h1 computed in 32-chunks ----
    u64 acc2p[8];
    #pragma unroll
    for (int j2 = 0; j2 < 8; j2++)
        acc2p[j2] = pk2(sbp2[q4*16 + 2*j2], sbp2[q4*16 + 2*j2+1]);

    #pragma unroll
    for (int chunk = 0; chunk < 2; chunk++) {
        u64 accp[16];
        #pragma unroll
        for (int j2 = 0; j2 < 16; j2++)
            accp[j2] = pk2(sbp1[chunk*32 + 2*j2], sbp1[chunk*32 + 2*j2+1]);
        #pragma unroll
        for (int r = 0; r < 9; r++) {
            u64 s2 = pk2(x9[r], x9[r]);
            #pragma unroll
            for (int k = 0; k < 8; k++) {
                ulonglong2 w = Wp1p[r*16 + chunk*8 + k];
                fma2(accp[2*k], s2, w.x); fma2(accp[2*k+1], s2, w.y);
            }
        }
        float h1c[32];
        #pragma unroll
        for (int j2 = 0; j2 < 16; j2++) upk2(accp[j2], h1c[2*j2], h1c[2*j2+1]);
        if (ms > 0) {
            #pragma unroll
            for (int jj = 0; jj < 32; jj++) h1c[jj] += sMp1[(chunk*32 + jj)*22 + m];
        }
        #pragma unroll
        for (int jj = 0; jj < 32; jj++) h1c[jj] = fmaxf(h1c[jj], 0.f);

        #pragma unroll 8
        for (int i = 0; i < 32; i++) {
            u64 s2 = pk2(h1c[i], h1c[i]);
            int c = chunk*32 + i;
            #pragma unroll
            for (int k = 0; k < 4; k++) {
                ulonglong2 w = Wp2p[c*16 + q4*4 + k];
                fma2(acc2p[2*k], s2, w.x); fma2(acc2p[2*k+1], s2, w.y);
            }
        }
    }
    // a4 partial over this quarter's 16 j's
    {
        float a0 = 0.f, a1 = 0.f, a2 = 0.f, a3 = 0.f;
        #pragma unroll
        for (int j2 = 0; j2 < 8; j2++) {
            float p0, p1;
            upk2(acc2p[j2], p0, p1);
            float ps0 = fmaxf(p0, 0.f) * mk;
            float ps1 = fmaxf(p1, 0.f) * mk;
            float4 wk0 = sWkqv[31 + q4*16 + 2*j2];
            float4 wk1 = sWkqv[31 + q4*16 + 2*j2 + 1];
            a0 += ps0*wk0.x + ps1*wk1.x; a1 += ps0*wk0.y + ps1*wk1.y;
            a2 += ps0*wk0.z + ps1*wk1.z; a3 += ps0*wk0.w + ps1*wk1.w;
        }
        ((float4*)sPa)[q4*128 + tok] = make_float4(a0, a1, a2, a3);
    }

    // ---- phi: outputs j in [q4*8, q4*8+8); f1 computed in 16-chunks ----
    u64 pp[4];
    #pragma unroll
    for (int j2 = 0; j2 < 4; j2++)
        pp[j2] = pk2(sbf2[q4*8 + 2*j2], sbf2[q4*8 + 2*j2+1]);

    #pragma unroll
    for (int chunk = 0; chunk < 2; chunk++) {
        u64 fp[8];
        #pragma unroll
        for (int j2 = 0; j2 < 8; j2++)
            fp[j2] = pk2(sbf1[chunk*16 + 2*j2], sbf1[chunk*16 + 2*j2+1]);
        #pragma unroll
        for (int r = 0; r < 9; r++) {
            u64 s2 = pk2(x9[r], x9[r]);
            #pragma unroll
            for (int k = 0; k < 4; k++) {
                ulonglong2 w = Wf1p[r*8 + chunk*4 + k];
                fma2(fp[2*k], s2, w.x); fma2(fp[2*k+1], s2, w.y);
            }
        }
        float f1c[16];
        #pragma unroll
        for (int j2 = 0; j2 < 8; j2++) upk2(fp[j2], f1c[2*j2], f1c[2*j2+1]);
        if (ms > 0) {
            #pragma unroll
            for (int jj = 0; jj < 16; jj++) f1c[jj] += sMf1[(chunk*16 + jj)*22 + m];
        }
        #pragma unroll
        for (int jj = 0; jj < 16; jj++) f1c[jj] = fmaxf(f1c[jj], 0.f);

        #pragma unroll 8
        for (int i = 0; i < 16; i++) {
            u64 s2 = pk2(f1c[i], f1c[i]);
            int c = chunk*16 + i;
            #pragma unroll
            for (int k = 0; k < 2; k++) {
                ulonglong2 w = Wf2p[c*8 + q4*2 + k];
                fma2(pp[2*k], s2, w.x); fma2(pp[2*k+1], s2, w.y);
            }
        }
    }
    {
        float4* phv = (float4*)(g_phi + (size_t)idx*32 + q4*8);
        float e0, e1, e2, e3;
        upk2(pp[0], e0, e1); upk2(pp[1], e2, e3);
        phv[0] = make_float4(fmaxf(e0,0.f)*mk, fmaxf(e1,0.f)*mk,
                             fmaxf(e2,0.f)*mk, fmaxf(e3,0.f)*mk);
        upk2(pp[2], e0, e1); upk2(pp[3], e2, e3);
        phv[1] = make_float4(fmaxf(e0,0.f)*mk, fmaxf(e1,0.f)*mk,
                             fmaxf(e2,0.f)*mk, fmaxf(e3,0.f)*mk);
    }

    __syncthreads();
    if (q4 == 0) {
        float4 p0 = ((float4*)sPa)[tok];
        float4 p1 = ((float4*)sPa)[128 + tok];
        float4 p2 = ((float4*)sPa)[256 + tok];
        float4 p3 = ((float4*)sPa)[384 + tok];
        ((float4*)g_a)[idx] = make_float4(p0.x+p1.x+p2.x+p3.x, p0.y+p1.y+p2.y+p3.y,
                                          p0.z+p1.z+p2.z+p3.z, p0.w+p1.w+p2.w+p3.w);
        float q0 = 0.f, q1 = 0.f, q2 = 0.f, q3 = 0.f;
        #pragma unroll
        for (int r = 0; r < 9; r++) {
            float4 wk = sWkqv[r];
            q0 += x9[r]*wk.x; q1 += x9[r]*wk.y; q2 += x9[r]*wk.z; q3 += x9[r]*wk.w;
        }
        if (ms > 0) {
            float4 wk = sWkqv[8 + ms];
            q0 += wk.x; q1 += wk.y; q2 += wk.z; q3 += wk.w;
        }
        ((float4*)g_xq)[idx] = make_float4(q0, q1, q2, q3);
    }
}

// ---------------------------------------------------------------- k_scan
__global__ void __launch_bounds__(1024) k_scan(const float* __restrict__ mask) {
    int b = blockIdx.x >> 2;
    int h = blockIdx.x & 3;
    int tid  = threadIdx.x;
    int warp = tid >> 5;
    int lane = tid & 31;
    int base = b * SEQ;
    const float inv_sqrt = 0.17677669529663688f;

    __shared__ float spre[SEQ];
    __shared__ float smk[SEQ];
    __shared__ float wsumA[32], wsumM[32];
    __shared__ float cS[32], cV[32*33];
    __shared__ float pS[32], pV[32*33];

    float bq = g_bq[h];

    float a  = g_a [(base+tid)*4 + h];
    float mk = mask[ base+tid ];
    float xq = g_xq[(base+tid)*4 + h];

    float A = a, Sm = mk;
    #pragma unroll
    for (int d = 1; d < 32; d <<= 1) {
        float tA = __shfl_up_sync(0xffffffffu, A, d);
        float tS = __shfl_up_sync(0xffffffffu, Sm, d);
        if (lane >= d) { A += tA; Sm += tS; }
    }
    if (lane == 31) { wsumA[warp] = A; wsumM[warp] = Sm; }
    __syncthreads();
    if (warp == 0) {
        float xA = wsumA[lane], xS = wsumM[lane];
        #pragma unroll
        for (int d = 1; d < 32; d <<= 1) {
            float tA = __shfl_up_sync(0xffffffffu, xA, d);
            float tS = __shfl_up_sync(0xffffffffu, xS, d);
            if (lane >= d) { xA += tA; xS += tS; }
        }
        wsumA[lane] = xA; wsumM[lane] = xS;
    }
    __syncthreads();
    if (warp > 0) { A += wsumA[warp-1]; Sm += wsumM[warp-1]; }

    spre[tid] = (xq + bq + __fdividef(A, Sm)) * inv_sqrt;
    smk[tid]  = mk;
    __syncthreads();

    float ph[32];
    float S = 0.f, V = 0.f;
    int p0 = warp * 32;
    #pragma unroll
    for (int i = 0; i < 32; i++) {
        int p = p0 + i;
        float w = __expf(spre[p]);
        float f = g_phi[(size_t)(base + p)*32 + lane];
        spre[p] = w;
        ph[i] = f;
        S += w;
        V += w*f;
    }
    if (lane == 0) cS[warp] = S;
    cV[warp*33 + lane] = V;
    __syncthreads();

    if (warp == 0) {
        float eS = 0.f, eV = 0.f;
        #pragma unroll
        for (int c = 0; c < 32; c++) {
            if (lane == 0) pS[c] = eS;
            pV[c*33 + lane] = eV;
            eS += cS[c];
            eV += cV[c*33 + lane];
        }
    }
    __syncthreads();

    S = pS[warp]; V = pV[warp*33 + lane];
    #pragma unroll
    for (int i = 0; i < 32; i++) {
        int p = p0 + i;
        float w = spre[p];
        S += w;
        V += w*ph[i];
        g_agg[(size_t)(base + p)*128 + h*32 + lane] = __fdividef(V, S) * smk[p];
    }
}

// ---------------------------------------------------------------- k_rho
// grid 128 x 512 thr, 128 tokens per block.
// Layer1: K split across ks = warp>>3 (K-half 64 each); partials combined in smem.
// Layer2: 2 tokens x 8 outputs per thread over full K=64.
#define RHO_PAD 132
#define HH_PAD  68
#define SU_FLOATS 17408         // max(128*RHO_PAD, 2*128*HH_PAD)
extern __shared__ float rho_smem[];
__global__ void __launch_bounds__(512) k_rho(
    const float* __restrict__ W1, const float* __restrict__ b1,
    const float* __restrict__ W2, const float* __restrict__ b2,
    const float* __restrict__ mask, float* __restrict__ out)
{
    float* sW1 = rho_smem;                  // 128*64
    float* sW2 = sW1 + 128*64;              // 64*64
    float* sU  = sW2 + 64*64;               // SU_FLOATS (acts, then partials/hh)
    float* sb1 = sU  + SU_FLOATS;
    float* sb2 = sb1 + 64;

    int tid  = threadIdx.x;
    int o    = tid & 7;                     // output octet 0..7
    int quad = (tid >> 3) & 31;             // token quad 0..31
    int ks   = tid >> 8;                    // K-half 0..1 (warp-uniform)
    int tok0 = blockIdx.x * 128;

    {
        const float4* w1g = (const float4*)W1;
        float4* d1 = (float4*)sW1;
        #pragma unroll 4
        for (int i = tid; i < 128*16; i += 512) d1[i] = w1g[i];
        const float4* w2g = (const float4*)W2;
        float4* d2 = (float4*)sW2;
        #pragma unroll 2
        for (int i = tid; i < 64*16; i += 512) d2[i] = w2g[i];
    }
    if (tid < 64) { sb1[tid] = b1[tid]; sb2[tid] = b2[tid]; }
    {
        const float4* src = (const float4*)(g_agg + (size_t)tok0*128);
        #pragma unroll 8
        for (int l4 = tid; l4 < 128*32; l4 += 512) {
            int tk = l4 >> 5, k4 = l4 & 31;
            ((float4*)(sU + tk*RHO_PAD))[k4] = src[l4];
        }
    }
    __syncthreads();

    // ---- layer 1: 4 tokens x 8 outputs over this thread's K-half (16 k4) ----
    u64 acc[4][4];
    #pragma unroll
    for (int t = 0; t < 4; t++)
        #pragma unroll
        for (int p = 0; p < 4; p++) acc[t][p] = 0ull;
    const ulonglong2* w1p = (const ulonglong2*)sW1;
    int k4base = ks * 16;
    for (int kk = 0; kk < 16; kk++) {
        int k4 = k4base + kk;
        float4 xa[4];
        #pragma unroll
        for (int t = 0; t < 4; t++)
            xa[t] = ((const float4*)(sU + (quad*4 + t)*RHO_PAD))[k4];
        #pragma unroll
        for (int e = 0; e < 4; e++) {
            int k = k4*4 + e;
            ulonglong2 wa = w1p[k*16 + o*2];
            ulonglong2 wb = w1p[k*16 + o*2 + 1];
            #pragma unroll
            for (int t = 0; t < 4; t++) {
                float s = (e==0)?xa[t].x:(e==1)?xa[t].y:(e==2)?xa[t].z:xa[t].w;
                u64 s2 = pk2(s, s);
                fma2(acc[t][0], s2, wa.x); fma2(acc[t][1], s2, wa.y);
                fma2(acc[t][2], s2, wb.x); fma2(acc[t][3], s2, wb.y);
            }
        }
    }
    float pr[4][8];
    #pragma unroll
    for (int t = 0; t < 4; t++)
        #pragma unroll
        for (int p = 0; p < 4; p++)
            upk2(acc[t][p], pr[t][2*p], pr[t][2*p+1]);

    __syncthreads();   // act reads done; reuse sU for partials
    #pragma unroll
    for (int t = 0; t < 4; t++) {
        float4* rP = (float4*)(sU + ks*128*HH_PAD + (quad*4 + t)*HH_PAD + o*8);
        rP[0] = make_float4(pr[t][0], pr[t][1], pr[t][2], pr[t][3]);
        rP[1] = make_float4(pr[t][4], pr[t][5], pr[t][6], pr[t][7]);
    }
    __syncthreads();

    // combine halves + bias + relu -> hh stored in ks=0 partial area
    for (int i = tid; i < 128*64; i += 512) {
        int tk = i >> 6, j = i & 63;
        float v = sU[tk*HH_PAD + j] + sU[128*HH_PAD + tk*HH_PAD + j] + sb1[j];
        sU[tk*HH_PAD + j] = fmaxf(v, 0.f);
    }
    __syncthreads();

    // ---- layer 2: 2 tokens x 8 outputs over full K=64 ----
    int tp = tid >> 3;                      // token pair 0..63
    u64 ac2[2][4];
    #pragma unroll
    for (int t = 0; t < 2; t++) {
        ac2[t][0] = pk2(sb2[o*8+0], sb2[o*8+1]);
        ac2[t][1] = pk2(sb2[o*8+2], sb2[o*8+3]);
        ac2[t][2] = pk2(sb2[o*8+4], sb2[o*8+5]);
        ac2[t][3] = pk2(sb2[o*8+6], sb2[o*8+7]);
    }
    const ulonglong2* w2p = (const ulonglong2*)sW2;
    for (int c4 = 0; c4 < 16; c4++) {
        float4 xa[2];
        #pragma unroll
        for (int t = 0; t < 2; t++)
            xa[t] = ((const float4*)(sU + (tp*2 + t)*HH_PAD))[c4];
        #pragma unroll
        for (int e = 0; e < 4; e++) {
            int c = c4*4 + e;
            ulonglong2 wa = w2p[c*16 + o*2];
            ulonglong2 wb = w2p[c*16 + o*2 + 1];
            #pragma unroll
            for (int t = 0; t < 2; t++) {
                float s = (e==0)?xa[t].x:(e==1)?xa[t].y:(e==2)?xa[t].z:xa[t].w;
                u64 s2 = pk2(s, s);
                fma2(ac2[t][0], s2, wa.x); fma2(ac2[t][1], s2, wa.y);
                fma2(ac2[t][2], s2, wb.x); fma2(ac2[t][3], s2, wb.y);
            }
        }
    }
    #pragma unroll
    for (int t = 0; t < 2; t++) {
        int tok = tok0 + tp*2 + t;
        float mk = mask[tok];
        float e0,e1,e2,e3,e4,e5,e6,e7;
        upk2(ac2[t][0], e0, e1); upk2(ac2[t][1], e2, e3);
        upk2(ac2[t][2], e4, e5); upk2(ac2[t][3], e6, e7);
        float4* op = (float4*)(out + (size_t)tok*64 + o*8);
        op[0] = make_float4(fmaxf(e0,0.f)*mk, fmaxf(e1,0.f)*mk,
                            fmaxf(e2,0.f)*mk, fmaxf(e3,0.f)*mk);
        op[1] = make_float4(fmaxf(e4,0.f)*mk, fmaxf(e5,0.f)*mk,
                            fmaxf(e6,0.f)*mk, fmaxf(e7,0.f)*mk);
    }
}

// ---------------------------------------------------------------- launch
extern "C" void kernel_launch(void* const* d_in, const int* in_sizes, int n_in,
                              void* d_out, int out_size) {
    (void)in_sizes; (void)n_in; (void)out_size;
    const float* times  = (const float*)d_in[0];
    const float* values = (const float*)d_in[1];
    const int*   meas   = (const int*)  d_in[2];
    const float* mask   = (const float*)d_in[3];
    const float* Wp1 = (const float*)d_in[4];  const float* bp1 = (const float*)d_in[5];
    const float* Wp2 = (const float*)d_in[6];  const float* bp2 = (const float*)d_in[7];
    const float* Wk  = (const float*)d_in[8];  const float* bk  = (const float*)d_in[9];
    const float* q   = (const float*)d_in[10];
    const float* Wf1 = (const float*)d_in[11]; const float* bf1 = (const float*)d_in[12];
    const float* Wf2 = (const float*)d_in[13]; const float* bf2 = (const float*)d_in[14];
    const float* Wr1 = (const float*)d_in[15]; const float* br1 = (const float*)d_in[16];
    const float* Wr2 = (const float*)d_in[17]; const float* br2 = (const float*)d_in[18];
    float* out = (float*)d_out;

    size_t rho_bytes = (128*64 + 64*64 + SU_FLOATS + 128 + 16) * sizeof(float);
    cudaFuncSetAttribute(k_rho, cudaFuncAttributeMaxDynamicSharedMemorySize, (int)rho_bytes);

    k_prep<<<1, 384>>>(Wk, bk, q);
    k_feat<<<128, 512>>>(times, values, meas, mask,
                         Wp1, bp1, Wp2, bp2, Wf1, bf1, Wf2, bf2);
    k_scan<<<BATCH*4, 1024>>>(mask);
    k_rho<<<128, 512, rho_bytes>>>(Wr1, br1, Wr2, br2, mask, out);
}

// round 15
// speedup vs baseline: 1.1102x; 1.1102x over previous
#include <cuda_runtime.h>

// DeepAttensionModule — SeFT cumulative set attention. (R12 config + pipelined rho)
//  k_prep : fold query into W_key  -> Wkq[95,4], bq[4]
//  k_feat : 256 thr: warps 0-3 = 128 tokens, half=warp>>2 splits psi2/phi2 outputs; FFMA2
//  k_scan : per (b,h) 1024-thread block; max-free prefix sums of (e^pre, e^pre*phi)
//  k_rho  : grid 128 x 256 thr, 4 tok x 8 out per thread, FFMA2, double-buffered acts

#define BATCH 16
#define SEQ   1024
#define NTOK  (BATCH*SEQ)
#define KEYIN 95

typedef unsigned long long u64;

__device__ __forceinline__ u64 pk2(float x, float y) {
    u64 r; asm("mov.b64 %0,{%1,%2};" : "=l"(r) : "f"(x), "f"(y)); return r;
}
__device__ __forceinline__ void upk2(u64 v, float& x, float& y) {
    asm("mov.b64 {%0,%1},%2;" : "=f"(x), "=f"(y) : "l"(v));
}
__device__ __forceinline__ void fma2(u64& d, u64 a, u64 b) {
    asm("fma.rn.f32x2 %0,%1,%2,%0;" : "+l"(d) : "l"(a), "l"(b));
}

__device__ float g_phi[NTOK*32];
__device__ float g_a[NTOK*4];
__device__ float g_xq[NTOK*4];
__device__ float g_agg[NTOK*128];
__device__ float g_Wkq[KEYIN*4];
__device__ float g_bq[4];

// ---------------------------------------------------------------- k_prep
__global__ void k_prep(const float* __restrict__ Wk, const float* __restrict__ bk,
                       const float* __restrict__ q) {
    int idx = threadIdx.x;
    if (idx < KEYIN*4) {
        int s = idx >> 2, h = idx & 3;
        float acc = 0.f;
        #pragma unroll
        for (int d = 0; d < 32; d++) acc += Wk[s*128 + h*32 + d] * q[h*32 + d];
        g_Wkq[idx] = acc;
    } else if (idx < KEYIN*4 + 4) {
        int h = idx - KEYIN*4;
        float acc = 0.f;
        #pragma unroll
        for (int d = 0; d < 32; d++) acc += bk[h*32 + d] * q[h*32 + d];
        g_bq[h] = acc;
    }
}

// ---------------------------------------------------------------- k_feat
// 256 threads, 128 tokens. warp 0-3 / 4-7 carry the same tokens (lane=token),
// half = warp>>2 selects the output-channel half of psi2/phi2.
__global__ void __launch_bounds__(256) k_feat(
    const float* __restrict__ times, const float* __restrict__ values,
    const int*   __restrict__ meas,  const float* __restrict__ mask,
    const float* __restrict__ Wp1, const float* __restrict__ bp1,
    const float* __restrict__ Wp2, const float* __restrict__ bp2,
    const float* __restrict__ Wf1, const float* __restrict__ bf1,
    const float* __restrict__ Wf2, const float* __restrict__ bf2)
{
    __shared__ __align__(16) float sWp1[9*64];
    __shared__ float sMp1[64*22];
    __shared__ __align__(16) float sWp2[64*64];
    __shared__ __align__(16) float sWf1[9*32];
    __shared__ float sMf1[32*22];
    __shared__ __align__(16) float sWf2[32*32];
    __shared__ __align__(16) float sWkq[KEYIN*4 + 4];
    __shared__ float sbp1[64], sbp2[64], sbf1[32], sbf2[32];
    __shared__ __align__(16) float sPa[2*128*4];

    int tid = threadIdx.x;
    for (int i = tid; i < 9*64;  i += 256) sWp1[i] = Wp1[i];
    for (int i = tid; i < 64*22; i += 256) { int j = i/22, m = i%22; sMp1[i] = Wp1[(9+m)*64 + j]; }
    for (int i = tid; i < 64*64; i += 256) sWp2[i] = Wp2[i];
    for (int i = tid; i < 9*32;  i += 256) sWf1[i] = Wf1[i];
    for (int i = tid; i < 32*22; i += 256) { int j = i/22, m = i%22; sMf1[i] = Wf1[(9+m)*32 + j]; }
    for (int i = tid; i < 32*32; i += 256) sWf2[i] = Wf2[i];
    for (int i = tid; i < KEYIN*4; i += 256) sWkq[i] = g_Wkq[i];
    if (tid < 64) { sbp1[tid] = bp1[tid]; sbp2[tid] = bp2[tid]; }
    if (tid < 32) { sbf1[tid] = bf1[tid]; sbf2[tid] = bf2[tid]; }
    __syncthreads();

    int warp = tid >> 5, lane = tid & 31;
    int half = warp >> 2;
    int tok  = (warp & 3) * 32 + lane;
    int idx  = blockIdx.x*128 + tok;

    float t  = times[idx];
    float v  = values[idx];
    float mk = mask[idx];
    int   ms = meas[idx];
    int   m  = ms - 1;

    float x9[9];
    x9[0] = sinf(t);          x9[1] = cosf(t);
    x9[2] = sinf(t*0.1f);     x9[3] = cosf(t*0.1f);
    x9[4] = sinf(t*0.01f);    x9[5] = cosf(t*0.01f);
    x9[6] = sinf(t*0.001f);   x9[7] = cosf(t*0.001f);
    x9[8] = v;

    const ulonglong2* Wp1p = (const ulonglong2*)sWp1;
    const ulonglong2* Wp2p = (const ulonglong2*)sWp2;
    const ulonglong2* Wf1p = (const ulonglong2*)sWf1;
    const ulonglong2* Wf2p = (const ulonglong2*)sWf2;
    const float4*     sWkqv = (const float4*)sWkq;

    // ---- psi layer 1 (full 64, duplicated across halves) ----
    u64 accp[32];
    #pragma unroll
    for (int j2 = 0; j2 < 32; j2++) accp[j2] = pk2(sbp1[2*j2], sbp1[2*j2+1]);
    #pragma unroll
    for (int r = 0; r < 9; r++) {
        u64 s2 = pk2(x9[r], x9[r]);
        #pragma unroll
        for (int k = 0; k < 16; k++) {
            ulonglong2 w = Wp1p[r*16 + k];
            fma2(accp[2*k], s2, w.x); fma2(accp[2*k+1], s2, w.y);
        }
    }
    float h1[64];
    #pragma unroll
    for (int j2 = 0; j2 < 32; j2++) upk2(accp[j2], h1[2*j2], h1[2*j2+1]);
    if (ms > 0) {
        #pragma unroll
        for (int j = 0; j < 64; j++) h1[j] += sMp1[j*22 + m];
    }
    #pragma unroll
    for (int j = 0; j < 64; j++) h1[j] = fmaxf(h1[j], 0.f);

    // ---- psi layer 2: only this half's 32 outputs (16 u64 pairs) ----
    u64 acc2p[16];
    #pragma unroll
    for (int j2 = 0; j2 < 16; j2++)
        acc2p[j2] = pk2(sbp2[half*32 + 2*j2], sbp2[half*32 + 2*j2+1]);
    #pragma unroll 8
    for (int c = 0; c < 64; c++) {
        u64 s2 = pk2(h1[c], h1[c]);
        #pragma unroll
        for (int k = 0; k < 8; k++) {
            ulonglong2 w = Wp2p[c*16 + half*8 + k];
            fma2(acc2p[2*k], s2, w.x); fma2(acc2p[2*k+1], s2, w.y);
        }
    }
    // a4 partial over this half's 32 j's
    {
        float a0 = 0.f, a1 = 0.f, a2 = 0.f, a3 = 0.f;
        #pragma unroll
        for (int j2 = 0; j2 < 16; j2++) {
            float p0, p1;
            upk2(acc2p[j2], p0, p1);
            float ps0 = fmaxf(p0, 0.f) * mk;
            float ps1 = fmaxf(p1, 0.f) * mk;
            float4 wk0 = sWkqv[31 + half*32 + 2*j2];
            float4 wk1 = sWkqv[31 + half*32 + 2*j2 + 1];
            a0 += ps0*wk0.x + ps1*wk1.x; a1 += ps0*wk0.y + ps1*wk1.y;
            a2 += ps0*wk0.z + ps1*wk1.z; a3 += ps0*wk0.w + ps1*wk1.w;
        }
        ((float4*)sPa)[half*128 + tok] = make_float4(a0, a1, a2, a3);
    }

    // ---- phi layer 1 (full 32, duplicated) ----
    u64 fp[16];
    #pragma unroll
    for (int j2 = 0; j2 < 16; j2++) fp[j2] = pk2(sbf1[2*j2], sbf1[2*j2+1]);
    #pragma unroll
    for (int r = 0; r < 9; r++) {
        u64 s2 = pk2(x9[r], x9[r]);
        #pragma unroll
        for (int k = 0; k < 8; k++) {
            ulonglong2 w = Wf1p[r*8 + k];
            fma2(fp[2*k], s2, w.x); fma2(fp[2*k+1], s2, w.y);
        }
    }
    float f1[32];
    #pragma unroll
    for (int j2 = 0; j2 < 16; j2++) upk2(fp[j2], f1[2*j2], f1[2*j2+1]);
    if (ms > 0) {
        #pragma unroll
        for (int j = 0; j < 32; j++) f1[j] += sMf1[j*22 + m];
    }
    #pragma unroll
    for (int j = 0; j < 32; j++) f1[j] = fmaxf(f1[j], 0.f);

    // ---- phi layer 2: only this half's 16 outputs (8 u64 pairs) ----
    u64 pp[8];
    #pragma unroll
    for (int j2 = 0; j2 < 8; j2++)
        pp[j2] = pk2(sbf2[half*16 + 2*j2], sbf2[half*16 + 2*j2+1]);
    #pragma unroll 8
    for (int c = 0; c < 32; c++) {
        u64 s2 = pk2(f1[c], f1[c]);
        #pragma unroll
        for (int k = 0; k < 4; k++) {
            ulonglong2 w = Wf2p[c*8 + half*4 + k];
            fma2(pp[2*k], s2, w.x); fma2(pp[2*k+1], s2, w.y);
        }
    }
    {
        float4* phv = (float4*)(g_phi + (size_t)idx*32 + half*16);
        #pragma unroll
        for (int j4 = 0; j4 < 4; j4++) {
            float e0, e1, e2, e3;
            upk2(pp[2*j4],   e0, e1);
            upk2(pp[2*j4+1], e2, e3);
            phv[j4] = make_float4(fmaxf(e0,0.f)*mk, fmaxf(e1,0.f)*mk,
                                  fmaxf(e2,0.f)*mk, fmaxf(e3,0.f)*mk);
        }
    }

    __syncthreads();
    if (half == 0) {
        float4 pa = ((float4*)sPa)[tok];
        float4 pb = ((float4*)sPa)[128 + tok];
        ((float4*)g_a)[idx] = make_float4(pa.x+pb.x, pa.y+pb.y, pa.z+pb.z, pa.w+pb.w);
        float q0 = 0.f, q1 = 0.f, q2 = 0.f, q3 = 0.f;
        #pragma unroll
        for (int r = 0; r < 9; r++) {
            float4 wk = sWkqv[r];
            q0 += x9[r]*wk.x; q1 += x9[r]*wk.y; q2 += x9[r]*wk.z; q3 += x9[r]*wk.w;
        }
        if (ms > 0) {
            float4 wk = sWkqv[8 + ms];
            q0 += wk.x; q1 += wk.y; q2 += wk.z; q3 += wk.w;
        }
        ((float4*)g_xq)[idx] = make_float4(q0, q1, q2, q3);
    }
}

// ---------------------------------------------------------------- k_scan
__global__ void __launch_bounds__(1024) k_scan(const float* __restrict__ mask) {
    int b = blockIdx.x >> 2;
    int h = blockIdx.x & 3;
    int tid  = threadIdx.x;
    int warp = tid >> 5;
    int lane = tid & 31;
    int base = b * SEQ;
    const float inv_sqrt = 0.17677669529663688f;

    __shared__ float spre[SEQ];
    __shared__ float smk[SEQ];
    __shared__ float wsumA[32], wsumM[32];
    __shared__ float cS[32], cV[32*33];
    __shared__ float pS[32], pV[32*33];

    float bq = g_bq[h];

    float a  = g_a [(base+tid)*4 + h];
    float mk = mask[ base+tid ];
    float xq = g_xq[(base+tid)*4 + h];

    float A = a, Sm = mk;
    #pragma unroll
    for (int d = 1; d < 32; d <<= 1) {
        float tA = __shfl_up_sync(0xffffffffu, A, d);
        float tS = __shfl_up_sync(0xffffffffu, Sm, d);
        if (lane >= d) { A += tA; Sm += tS; }
    }
    if (lane == 31) { wsumA[warp] = A; wsumM[warp] = Sm; }
    __syncthreads();
    if (warp == 0) {
        float xA = wsumA[lane], xS = wsumM[lane];
        #pragma unroll
        for (int d = 1; d < 32; d <<= 1) {
            float tA = __shfl_up_sync(0xffffffffu, xA, d);
            float tS = __shfl_up_sync(0xffffffffu, xS, d);
            if (lane >= d) { xA += tA; xS += tS; }
        }
        wsumA[lane] = xA; wsumM[lane] = xS;
    }
    __syncthreads();
    if (warp > 0) { A += wsumA[warp-1]; Sm += wsumM[warp-1]; }

    spre[tid] = (xq + bq + __fdividef(A, Sm)) * inv_sqrt;
    smk[tid]  = mk;
    __syncthreads();

    float ph[32];
    float S = 0.f, V = 0.f;
    int p0 = warp * 32;
    #pragma unroll
    for (int i = 0; i < 32; i++) {
        int p = p0 + i;
        float w = __expf(spre[p]);
        float f = g_phi[(size_t)(base + p)*32 + lane];
        spre[p] = w;
        ph[i] = f;
        S += w;
        V += w*f;
    }
    if (lane == 0) cS[warp] = S;
    cV[warp*33 + lane] = V;
    __syncthreads();

    if (warp == 0) {
        float eS = 0.f, eV = 0.f;
        #pragma unroll
        for (int c = 0; c < 32; c++) {
            if (lane == 0) pS[c] = eS;
            pV[c*33 + lane] = eV;
            eS += cS[c];
            eV += cV[c*33 + lane];
        }
    }
    __syncthreads();

    S = pS[warp]; V = pV[warp*33 + lane];
    #pragma unroll
    for (int i = 0; i < 32; i++) {
        int p = p0 + i;
        float w = spre[p];
        S += w;
        V += w*ph[i];
        g_agg[(size_t)(base + p)*128 + h*32 + lane] = __fdividef(V, S) * smk[p];
    }
}

// ---------------------------------------------------------------- k_rho
// 256 threads: 32 token-quads x 8 output-octets. 4 tokens x 8 outputs per thread.
// Double-buffered activation loads hide LDS latency.
#define RHO_PAD 132
#define HH_PAD  68
extern __shared__ float rho_smem[];
__global__ void __launch_bounds__(256) k_rho(
    const float* __restrict__ W1, const float* __restrict__ b1,
    const float* __restrict__ W2, const float* __restrict__ b2,
    const float* __restrict__ mask, float* __restrict__ out)
{
    float* sW1 = rho_smem;                  // 128*64
    float* sW2 = sW1 + 128*64;              // 64*64
    float* sA  = sW2 + 64*64;               // 128*RHO_PAD (reused as sHH)
    float* sb1 = sA  + 128*RHO_PAD;
    float* sb2 = sb1 + 64;
    float* sHH = sA;

    int tid  = threadIdx.x;
    int o    = tid & 7;                     // output octet
    int quad = tid >> 3;                    // token quad 0..31
    int tok0 = blockIdx.x * 128;

    {
        const float4* w1g = (const float4*)W1;
        float4* d1 = (float4*)sW1;
        #pragma unroll 4
        for (int i = tid; i < 128*16; i += 256) d1[i] = w1g[i];
        const float4* w2g = (const float4*)W2;
        float4* d2 = (float4*)sW2;
        #pragma unroll 4
        for (int i = tid; i < 64*16; i += 256) d2[i] = w2g[i];
    }
    if (tid < 64) { sb1[tid] = b1[tid]; sb2[tid] = b2[tid]; }
    {
        const float4* src = (const float4*)(g_agg + (size_t)tok0*128);
        #pragma unroll 8
        for (int l4 = tid; l4 < 128*32; l4 += 256) {
            int tk = l4 >> 5, k4 = l4 & 31;
            ((float4*)(sA + tk*RHO_PAD))[k4] = src[l4];
        }
    }
    __syncthreads();

    // ---- layer 1: 4 tokens x 8 outputs over K=128, pipelined acts ----
    u64 acc[4][4];
    #pragma unroll
    for (int t = 0; t < 4; t++)
        #pragma unroll
        for (int p = 0; p < 4; p++) acc[t][p] = 0ull;
    const ulonglong2* w1p = (const ulonglong2*)sW1;

    float4 xa[4];
    #pragma unroll
    for (int t = 0; t < 4; t++)
        xa[t] = ((const float4*)(sA + (quad*4 + t)*RHO_PAD))[0];

    for (int k4 = 0; k4 < 32; k4++) {
        float4 xn[4];
        if (k4 < 31) {
            #pragma unroll
            for (int t = 0; t < 4; t++)
                xn[t] = ((const float4*)(sA + (quad*4 + t)*RHO_PAD))[k4 + 1];
        }
        #pragma unroll
        for (int e = 0; e < 4; e++) {
            int k = k4*4 + e;
            ulonglong2 wa = w1p[k*16 + o*2];
            ulonglong2 wb = w1p[k*16 + o*2 + 1];
            #pragma unroll
            for (int t = 0; t < 4; t++) {
                float s = (e==0)?xa[t].x:(e==1)?xa[t].y:(e==2)?xa[t].z:xa[t].w;
                u64 s2 = pk2(s, s);
                fma2(acc[t][0], s2, wa.x); fma2(acc[t][1], s2, wa.y);
                fma2(acc[t][2], s2, wb.x); fma2(acc[t][3], s2, wb.y);
            }
        }
        if (k4 < 31) {
            #pragma unroll
            for (int t = 0; t < 4; t++) xa[t] = xn[t];
        }
    }
    float hh[4][8];
    #pragma unroll
    for (int t = 0; t < 4; t++)
        #pragma unroll
        for (int p = 0; p < 4; p++) {
            float e0, e1; upk2(acc[t][p], e0, e1);
            hh[t][2*p]   = fmaxf(e0 + sb1[o*8 + 2*p],   0.f);
            hh[t][2*p+1] = fmaxf(e1 + sb1[o*8 + 2*p+1], 0.f);
        }

    __syncthreads();
    #pragma unroll
    for (int t = 0; t < 4; t++) {
        float4* rH = (float4*)(sHH + (quad*4 + t)*HH_PAD + o*8);
        rH[0] = make_float4(hh[t][0], hh[t][1], hh[t][2], hh[t][3]);
        rH[1] = make_float4(hh[t][4], hh[t][5], hh[t][6], hh[t][7]);
    }
    __syncthreads();

    // ---- layer 2: over K=64, pipelined acts ----
    #pragma unroll
    for (int t = 0; t < 4; t++) {
        acc[t][0] = pk2(sb2[o*8+0], sb2[o*8+1]);
        acc[t][1] = pk2(sb2[o*8+2], sb2[o*8+3]);
        acc[t][2] = pk2(sb2[o*8+4], sb2[o*8+5]);
        acc[t][3] = pk2(sb2[o*8+6], sb2[o*8+7]);
    }
    const ulonglong2* w2p = (const ulonglong2*)sW2;

    #pragma unroll
    for (int t = 0; t < 4; t++)
        xa[t] = ((const float4*)(sHH + (quad*4 + t)*HH_PAD))[0];

    for (int c4 = 0; c4 < 16; c4++) {
        float4 xn[4];
        if (c4 < 15) {
            #pragma unroll
            for (int t = 0; t < 4; t++)
                xn[t] = ((const float4*)(sHH + (quad*4 + t)*HH_PAD))[c4 + 1];
        }
        #pragma unroll
        for (int e = 0; e < 4; e++) {
            int c = c4*4 + e;
            ulonglong2 wa = w2p[c*16 + o*2];
            ulonglong2 wb = w2p[c*16 + o*2 + 1];
            #pragma unroll
            for (int t = 0; t < 4; t++) {
                float s = (e==0)?xa[t].x:(e==1)?xa[t].y:(e==2)?xa[t].z:xa[t].w;
                u64 s2 = pk2(s, s);
                fma2(acc[t][0], s2, wa.x); fma2(acc[t][1], s2, wa.y);
                fma2(acc[t][2], s2, wb.x); fma2(acc[t][3], s2, wb.y);
            }
        }
        if (c4 < 15) {
            #pragma unroll
            for (int t = 0; t < 4; t++) xa[t] = xn[t];
        }
    }
    #pragma unroll
    for (int t = 0; t < 4; t++) {
        int tok = tok0 + quad*4 + t;
        float mk = mask[tok];
        float e0,e1,e2,e3,e4,e5,e6,e7;
        upk2(acc[t][0], e0, e1); upk2(acc[t][1], e2, e3);
        upk2(acc[t][2], e4, e5); upk2(acc[t][3], e6, e7);
        float4* op = (float4*)(out + (size_t)tok*64 + o*8);
        op[0] = make_float4(fmaxf(e0,0.f)*mk, fmaxf(e1,0.f)*mk,
                            fmaxf(e2,0.f)*mk, fmaxf(e3,0.f)*mk);
        op[1] = make_float4(fmaxf(e4,0.f)*mk, fmaxf(e5,0.f)*mk,
                            fmaxf(e6,0.f)*mk, fmaxf(e7,0.f)*mk);
    }
}

// ---------------------------------------------------------------- launch
extern "C" void kernel_launch(void* const* d_in, const int* in_sizes, int n_in,
                              void* d_out, int out_size) {
    (void)in_sizes; (void)n_in; (void)out_size;
    const float* times  = (const float*)d_in[0];
    const float* values = (const float*)d_in[1];
    const int*   meas   = (const int*)  d_in[2];
    const float* mask   = (const float*)d_in[3];
    const float* Wp1 = (const float*)d_in[4];  const float* bp1 = (const float*)d_in[5];
    const float* Wp2 = (const float*)d_in[6];  const float* bp2 = (const float*)d_in[7];
    const float* Wk  = (const float*)d_in[8];  const float* bk  = (const float*)d_in[9];
    const float* q   = (const float*)d_in[10];
    const float* Wf1 = (const float*)d_in[11]; const float* bf1 = (const float*)d_in[12];
    const float* Wf2 = (const float*)d_in[13]; const float* bf2 = (const float*)d_in[14];
    const float* Wr1 = (const float*)d_in[15]; const float* br1 = (const float*)d_in[16];
    const float* Wr2 = (const float*)d_in[17]; const float* br2 = (const float*)d_in[18];
    float* out = (float*)d_out;

    size_t rho_bytes = (128*64 + 64*64 + 128*RHO_PAD + 128 + 16) * sizeof(float);
    cudaFuncSetAttribute(k_rho, cudaFuncAttributeMaxDynamicSharedMemorySize, (int)rho_bytes);

    k_prep<<<1, 384>>>(Wk, bk, q);
    k_feat<<<128, 256>>>(times, values, meas, mask,
                         Wp1, bp1, Wp2, bp2, Wf1, bf1, Wf2, bf2);
    k_scan<<<BATCH*4, 1024>>>(mask);
    k_rho<<<128, 256, rho_bytes>>>(Wr1, br1, Wr2, br2, mask, out);
}